// round 9
// baseline (speedup 1.0000x reference)
#include <cuda_runtime.h>

// out[b, f] = x0[b, f] * dot(x[b,:], w) + bias[f] + x[b, f]
// B = 16384 rows, F = 2048 cols, fp32. One CTA per row, 256 threads,
// each thread owns 8 columns (2 x float4).
//
// FINAL (R9 = R8 + 32-bit indexing):
//  - 32 regs == EXACT occ-8 register-file cap (8 CTA x 256 thr x 32 =
//    65536 regs/SM). Every variant that front-batched x0 (+8 live regs)
//    lost occupancy and wall time; this shape measured best (61.47us).
//  - x / w loaded first (dot-critical); x0 / bias in the epilogue.
//  - Single __syncthreads; warp partials summed via broadcast LDS.
//  - 32-bit indices (max byte offset 2^27 < 2^31): removes 64-bit IMAD
//    chains and frees reg/ALU headroom inside the 32-reg budget.
//  - Measured-and-rejected: ldcs/stcs, persistent grid, 512-thr CTAs,
//    2 rows/CTA, full front-batching. All plateau at DRAM 81-83%
//    (~6.5 TB/s) == HBM3e mixed R/W ceiling; 384 MiB traffic irreducible.

#define F_DIM 2048
#define VEC_PER_ROW (F_DIM / 4)   // 512 float4
#define THREADS 256
#define NWARPS (THREADS / 32)

__global__ __launch_bounds__(THREADS, 8)
void cross_fused_kernel(const float4* __restrict__ x0,
                        const float4* __restrict__ x,
                        const float4* __restrict__ w,
                        const float4* __restrict__ bias,
                        float4* __restrict__ out)
{
    const int tid  = threadIdx.x;
    const int base = blockIdx.x * VEC_PER_ROW;   // max 16384*512 = 2^23

    const int i0 = base + tid;
    const int i1 = i0 + THREADS;

    // Dot-critical loads first.
    float4 xa = x[i0];
    float4 xb = x[i1];
    float4 wa = w[tid];
    float4 wb = w[tid + THREADS];

    // Per-thread partial dot.
    float s = xa.x * wa.x + xa.y * wa.y + xa.z * wa.z + xa.w * wa.w
            + xb.x * wb.x + xb.y * wb.y + xb.z * wb.z + xb.w * wb.w;

    // Warp reduce.
    #pragma unroll
    for (int off = 16; off > 0; off >>= 1)
        s += __shfl_xor_sync(0xFFFFFFFFu, s, off);

    // Single-barrier cross-warp reduce: lane 0 publishes, everyone sums.
    __shared__ float warp_sums[NWARPS];
    const int lane = tid & 31;
    const int warp = tid >> 5;
    if (lane == 0) warp_sums[warp] = s;
    __syncthreads();

    float xw = 0.0f;
    #pragma unroll
    for (int i = 0; i < NWARPS; i++)
        xw += warp_sums[i];   // broadcast LDS, conflict-free

    // Epilogue loads (placed by ptxas within the 32-reg budget).
    float4 x0a = x0[i0];
    float4 x0b = x0[i1];
    float4 ba  = bias[tid];
    float4 bb  = bias[tid + THREADS];

    // out = x0 * xw + bias + x
    float4 oa, ob;
    oa.x = fmaf(x0a.x, xw, ba.x + xa.x);
    oa.y = fmaf(x0a.y, xw, ba.y + xa.y);
    oa.z = fmaf(x0a.z, xw, ba.z + xa.z);
    oa.w = fmaf(x0a.w, xw, ba.w + xa.w);
    ob.x = fmaf(x0b.x, xw, bb.x + xb.x);
    ob.y = fmaf(x0b.y, xw, bb.y + xb.y);
    ob.z = fmaf(x0b.z, xw, bb.z + xb.z);
    ob.w = fmaf(x0b.w, xw, bb.w + xb.w);

    out[i0] = oa;
    out[i1] = ob;
}

extern "C" void kernel_launch(void* const* d_in, const int* in_sizes, int n_in,
                              void* d_out, int out_size)
{
    const float4* x0   = (const float4*)d_in[0];
    const float4* x    = (const float4*)d_in[1];
    const float4* w    = (const float4*)d_in[2];
    const float4* bias = (const float4*)d_in[3];
    float4* out = (float4*)d_out;

    const int rows = in_sizes[0] / F_DIM;  // 16384
    cross_fused_kernel<<<rows, THREADS>>>(x0, x, w, bias, out);
}